// round 10
// baseline (speedup 1.0000x reference)
#include <cuda_runtime.h>
#include <cstdint>

#define BATCH   8
#define NANCH   25200
#define NCH     85
#define TOPK    1000
#define KPAD    1024
#define NCLS    80
#define CONF_TH 0.25f
#define IOU_TH  0.45f
#define MAX_WH  4096.0f
#define NB14    16384
#define CAP     8192
#define RSTR    33

// ---------------- scratch (device globals; no allocation) ----------------
__device__ unsigned           g_enc [BATCH * NANCH];
__device__ unsigned           g_hist[BATCH * NB14];   // zeroed by k_pick after use
__device__ unsigned long long g_cand[BATCH * CAP];
__device__ unsigned long long g_sel [BATCH * KPAD];
__device__ unsigned           g_ccnt[BATCH];          // zeroed by k_sel after use
__device__ unsigned           g_scnt[BATCH];          // zeroed by k_post after use
__device__ unsigned           g_bucket[BATCH];
__device__ unsigned           g_need[BATCH];
__device__ unsigned long long g_T64[BATCH];           // 0 = not yet known

// ---------------- K1: score = obj * max(cls); encode; fused 14-bit histogram ----------------
#define SB 128
__global__ void __launch_bounds__(SB) k_score(const float* __restrict__ x) {
    __shared__ float sx[SB * NCH];
    const int tid = threadIdx.x;
    const size_t base = (size_t)blockIdx.x * SB * NCH;
    const float4* xv = (const float4*)(x + base);
    #pragma unroll
    for (int t = tid; t < SB * NCH / 4; t += SB) ((float4*)sx)[t] = xv[t];
    __syncthreads();

    const int a = blockIdx.x * SB + tid;
    const float* p = sx + tid * NCH;
    float obj = p[4];
    float m = p[5];
    #pragma unroll 16
    for (int c = 1; c < NCLS; ++c) m = fmaxf(m, p[5 + c]);
    float sc = __fmul_rn(obj, m);
    unsigned u = __float_as_uint((sc > CONF_TH) ? sc : -1.0f);
    unsigned e = (u & 0x80000000u) ? ~u : (u | 0x80000000u);
    g_enc[a] = e;

    int b = a / NANCH;
    unsigned addr = (unsigned)b * NB14 + (e >> 18);
    unsigned mm = __match_any_sync(0xffffffffu, addr);
    if ((tid & 31) == (__ffs(mm) - 1))
        atomicAdd(&g_hist[addr], (unsigned)__popc(mm));
}

// ---------------- K2a: boundary bucket via warp-shuffle suffix scan ----------------
__global__ void __launch_bounds__(1024) k_pick() {
    const int b = blockIdx.x, tid = threadIdx.x;
    const int wid = tid >> 5, lane = tid & 31;
    __shared__ unsigned hstage[NB14];
    __shared__ unsigned s_w[32];
    #pragma unroll
    for (int q = 0; q < 16; ++q) {
        int i = tid + q * 1024;
        hstage[i] = g_hist[b * NB14 + i];
        g_hist[b * NB14 + i] = 0u;          // coalesced self-clean
    }
    __syncthreads();

    unsigned lv[16];
    const int base16 = tid * 16;
    #pragma unroll
    for (int i = 0; i < 16; ++i) lv[i] = hstage[base16 + i];
    unsigned run = 0;
    #pragma unroll
    for (int i = 15; i >= 0; --i) { run += lv[i]; lv[i] = run; }
    const unsigned ttot = run;
    unsigned v = ttot;
    #pragma unroll
    for (int off = 1; off < 32; off <<= 1) {
        unsigned t = __shfl_down_sync(0xffffffffu, v, off);
        if (lane + off < 32) v += t;
    }
    if (lane == 0) s_w[wid] = v;
    __syncthreads();
    if (tid < 32) {
        unsigned u0 = s_w[tid], w = u0;
        #pragma unroll
        for (int off = 1; off < 32; off <<= 1) {
            unsigned t = __shfl_down_sync(0xffffffffu, w, off);
            if (tid + off < 32) w += t;
        }
        s_w[tid] = w - u0;                  // exclusive suffix over higher warps
    }
    __syncthreads();
    {
        unsigned above = s_w[wid] + (v - ttot);
        #pragma unroll
        for (int i = 0; i < 16; ++i) {
            unsigned tot = above + lv[i];
            unsigned cnt = lv[i] - ((i < 15) ? lv[i + 1] : 0u);
            unsigned gt  = tot - cnt;
            if (gt < TOPK && TOPK <= tot) {
                unsigned need = TOPK - gt;
                g_bucket[b] = (unsigned)(base16 + i);
                g_need[b]   = need;
                g_T64[b]    = (need == cnt)
                              ? ((unsigned long long)(base16 + i) << 50) : 0ull;
            }
        }
    }
}

// ---------------- K2b: compact boundary-bucket candidates (grid-wide) ----------------
__global__ void __launch_bounds__(1024) k_cand() {
    const int b = blockIdx.y;
    if (g_T64[b] != 0ull) return;           // already exact
    const int i = blockIdx.x * 1024 + threadIdx.x;
    if (i >= NANCH) return;
    unsigned e = g_enc[b * NANCH + i];
    if ((e >> 18) == g_bucket[b]) {
        unsigned pos = atomicAdd(&g_ccnt[b], 1u);
        if (pos < CAP)
            g_cand[b * CAP + pos] =
                ((unsigned long long)e << 32) | (unsigned)(~(unsigned)i);
    }
}

// ---------------- K2c: rank-by-count -> exact 1000th key ----------------
#define SEL_CAND  0        // u64[CAP] = 64KB
#define SEL_HIST2 65536    // u32[2048]
#define SEL_SCN2  73728    // u32[2048]
#define SEL_SMEM  81920
__global__ void __launch_bounds__(1024) k_sel() {
    const int b = blockIdx.x, tid = threadIdx.x;
    if (g_T64[b] != 0ull) return;
    extern __shared__ unsigned char smraw[];
    unsigned long long* cand  = (unsigned long long*)(smraw + SEL_CAND);
    unsigned*           hist2 = (unsigned*)(smraw + SEL_HIST2);
    unsigned*           scn2  = (unsigned*)(smraw + SEL_SCN2);
    __shared__ unsigned s_ctrl[4];
    __shared__ unsigned long long s_T64;

    unsigned M0 = g_ccnt[b];
    unsigned need = g_need[b];
    unsigned C;
    if (M0 <= CAP) {
        C = M0;
        for (unsigned j = tid; j < C; j += 1024) cand[j] = g_cand[b * CAP + j];
        __syncthreads();
    } else {
        // rare: refine bucket over g_enc until candidates fit CAP, then compact
        const unsigned* encb = g_enc + b * NANCH;
        unsigned long long prefix = (unsigned long long)g_bucket[b];
        int shift = 50;
        unsigned count = M0;
        while (count > CAP) {
            int w = (shift >= 11) ? 11 : shift;
            int s2 = shift - w;
            unsigned dmask = (1u << w) - 1u;
            for (int t = tid; t < 2048; t += 1024) hist2[t] = 0u;
            __syncthreads();
            for (int it = 0; it < 25; ++it) {
                int i = tid + it * 1024;
                if (i < NANCH) {
                    unsigned long long key =
                        ((unsigned long long)encb[i] << 32) | (unsigned)(~(unsigned)i);
                    if ((key >> shift) == prefix)
                        atomicAdd(&hist2[(unsigned)((key >> s2) & dmask)], 1u);
                }
            }
            __syncthreads();
            for (int t = tid; t < 2048; t += 1024) scn2[t] = hist2[t];
            __syncthreads();
            for (int d = 1; d < 2048; d <<= 1) {
                unsigned a0 = (tid + d < 2048) ? scn2[tid + d] : 0u;
                unsigned a1 = (tid + 1024 + d < 2048) ? scn2[tid + 1024 + d] : 0u;
                __syncthreads();
                scn2[tid] += a0; scn2[tid + 1024] += a1;
                __syncthreads();
            }
            #pragma unroll
            for (int q = 0; q < 2; ++q) {
                int d = tid + q * 1024;
                unsigned tot = scn2[d], gt = tot - hist2[d];
                if (gt < need && need <= tot) {
                    s_ctrl[0] = (unsigned)d;
                    s_ctrl[1] = need - gt;
                    s_ctrl[2] = hist2[d];
                }
            }
            __syncthreads();
            prefix = (prefix << w) | (unsigned long long)s_ctrl[0];
            need = s_ctrl[1]; count = s_ctrl[2]; shift = s2;
            __syncthreads();
        }
        if (tid == 0) s_ctrl[3] = 0u;
        __syncthreads();
        for (int it = 0; it < 25; ++it) {
            int i = tid + it * 1024;
            if (i < NANCH) {
                unsigned long long key =
                    ((unsigned long long)encb[i] << 32) | (unsigned)(~(unsigned)i);
                if ((key >> shift) == prefix) {
                    unsigned pos = atomicAdd(&s_ctrl[3], 1u);
                    if (pos < CAP) cand[pos] = key;
                }
            }
        }
        __syncthreads();
        C = s_ctrl[3];
    }

    // rank-by-count: the key with exactly (need-1) greater keys in the bucket
    for (unsigned j = tid; j < C; j += 1024) {
        unsigned long long kj = cand[j];
        unsigned gt = 0;
        for (unsigned k = 0; k < C; ++k) gt += (cand[k] > kj);
        if (gt == need - 1) s_T64 = kj;
    }
    __syncthreads();
    if (tid == 0) { g_T64[b] = s_T64; g_ccnt[b] = 0u; }   // self-clean
}

// ---------------- K2d: collect the exactly-1000 keys >= T64 (grid-wide) ----------------
__global__ void __launch_bounds__(1024) k_coll() {
    const int b = blockIdx.y;
    const int i = blockIdx.x * 1024 + threadIdx.x;
    if (i >= NANCH) return;
    unsigned e = g_enc[b * NANCH + i];
    unsigned long long key = ((unsigned long long)e << 32) | (unsigned)(~(unsigned)i);
    if (key >= g_T64[b]) {
        unsigned pos = atomicAdd(&g_scnt[b], 1u);
        if (pos < KPAD) g_sel[b * KPAD + pos] = key;
    }
}

// ---------------- K3: sort + gather + class-sparse IoU + greedy scan + output ----------------
#define PO_ROWS   0
#define PO_BOXO   135168
#define PO_BOXP   151552
#define PO_AREA   167936
#define PO_SCORE  172032
#define PO_CLSF   176128
#define PO_CLIST  180224
#define PO_CBASE  184320
#define PO_COFF   184832
#define PO_KEEPW  185344
#define PO_OUTK   185472
#define K3_SMEM   193664

__global__ void __launch_bounds__(1024) k_post(const float* __restrict__ x,
                                               float* __restrict__ out) {
    const int b   = blockIdx.x;
    const int tid = threadIdx.x;
    const int lane = tid & 31;
    extern __shared__ unsigned char sm[];
    unsigned* rows  = (unsigned*)(sm + PO_ROWS);
    float4*   boxo  = (float4*)  (sm + PO_BOXO);
    float4*   boxp  = (float4*)  (sm + PO_BOXP);
    float*    area  = (float*)   (sm + PO_AREA);
    float*    score = (float*)   (sm + PO_SCORE);
    float*    clsf  = (float*)   (sm + PO_CLSF);
    int*      clist = (int*)     (sm + PO_CLIST);
    int*      cbase = (int*)     (sm + PO_CBASE);
    int*      coff  = (int*)     (sm + PO_COFF);
    unsigned* keepw = (unsigned*)(sm + PO_KEEPW);
    unsigned long long* outk = (unsigned long long*)(sm + PO_OUTK);

    // load keys, pad, bitonic sort desc (distinct keys; zeros sink to tail)
    unsigned n = g_scnt[b];
    outk[tid] = (tid < (int)n) ? g_sel[b * KPAD + tid] : 0ull;
    __syncthreads();
    for (unsigned kk = 2; kk <= 1024; kk <<= 1) {
        for (unsigned j = kk >> 1; j > 0; j >>= 1) {
            unsigned i = (unsigned)tid, ixj = i ^ j;
            if (ixj > i) {
                unsigned long long a = outk[i], bb = outk[ixj];
                bool desc = ((i & kk) == 0);
                if (desc ? (a < bb) : (a > bb)) { outk[i] = bb; outk[ixj] = a; }
            }
            __syncthreads();
        }
    }

    // zero bitmat + counters
    for (int t = tid; t < KPAD * RSTR; t += 1024) rows[t] = 0u;
    if (tid < NCLS) coff[tid] = 0;
    if (tid < 32)   keepw[tid] = 0u;

    // decode + gather + per-row argmax
    unsigned long long key = outk[tid];
    float sc = -1.0f;
    int   idx = 0;
    if (key != 0ull) {
        unsigned e = (unsigned)(key >> 32);
        unsigned u = (e & 0x80000000u) ? (e ^ 0x80000000u) : ~e;
        sc = __uint_as_float(u);
        idx = (int)(~(unsigned)(key & 0xffffffffull));
    }
    score[tid] = sc;
    int c = -1;
    if (tid < TOPK && key != 0ull) {
        const float* p = x + ((size_t)b * NANCH + idx) * NCH;
        float cx = p[0], cy = p[1], w = p[2], h = p[3];
        float best = p[5]; int bi = 0;
        #pragma unroll 8
        for (int cc = 1; cc < NCLS; ++cc) {
            float vv = p[5 + cc];
            if (vv > best) { best = vv; bi = cc; }   // strict >: lowest index on ties
        }
        c = bi;
        float hw = __fmul_rn(w, 0.5f), hh = __fmul_rn(h, 0.5f);
        float x1 = __fsub_rn(cx, hw), y1 = __fsub_rn(cy, hh);
        float x2 = __fadd_rn(cx, hw), y2 = __fadd_rn(cy, hh);
        float cf = (float)c;
        float o  = __fmul_rn(cf, MAX_WH);
        float ox1 = __fadd_rn(x1, o), oy1 = __fadd_rn(y1, o);
        float ox2 = __fadd_rn(x2, o), oy2 = __fadd_rn(y2, o);
        boxp[tid] = make_float4(x1, y1, x2, y2);
        boxo[tid] = make_float4(ox1, oy1, ox2, oy2);
        area[tid] = __fmul_rn(__fsub_rn(ox2, ox1), __fsub_rn(oy2, oy1));
        clsf[tid] = cf;
    } else {
        boxp[tid] = make_float4(0.f, 0.f, 0.f, 0.f);
        boxo[tid] = make_float4(0.f, 0.f, 0.f, 0.f);
        area[tid] = 0.f; clsf[tid] = 0.f;
    }
    int V = __syncthreads_count(tid < TOPK && sc > CONF_TH);

    // counting sort by class (cross-class IoU is exactly 0: offsets >= 4096 >> extent)
    if (c >= 0) atomicAdd(&coff[c], 1);
    __syncthreads();
    if (tid == 0) {
        int r2 = 0;
        #pragma unroll
        for (int k = 0; k < NCLS; ++k) { cbase[k] = r2; r2 += coff[k]; }
        cbase[NCLS] = r2;
    }
    __syncthreads();
    if (tid < NCLS) coff[tid] = cbase[tid];
    __syncthreads();
    if (c >= 0) clist[atomicAdd(&coff[c], 1)] = tid;
    __syncthreads();

    // sparse IoU (reference fp32 arithmetic, FMA-free)
    if (c >= 0) {
        float4 bi4 = boxo[tid];
        float  ai  = area[tid];
        int k0 = cbase[c], k1 = cbase[c + 1];
        for (int k = k0; k < k1; ++k) {
            int j = clist[k];
            if (j == tid) continue;
            float4 bj = boxo[j];
            float ww = fmaxf(__fsub_rn(fminf(bi4.z, bj.z), fmaxf(bi4.x, bj.x)), 0.0f);
            float hh = fmaxf(__fsub_rn(fminf(bi4.w, bj.w), fmaxf(bi4.y, bj.y)), 0.0f);
            float inter = __fmul_rn(ww, hh);
            float den = __fadd_rn(__fsub_rn(__fadd_rn(ai, area[j]), inter), 1e-9f);
            if (__fdiv_rn(inter, den) > IOU_TH)
                rows[tid * RSTR + (j >> 5)] |= (1u << (j & 31));
        }
    }
    __syncthreads();

    // windowed greedy scan (warp 0)
    if (tid < 32) {
        int nwin = (V + 31) >> 5;
        unsigned supp = 0;
        for (int widx = 0; widx < nwin; ++widx) {
            int i0 = widx << 5;
            int lim = V - i0;
            unsigned vmask = (lim >= 32) ? 0xffffffffu : ((1u << lim) - 1u);
            unsigned dw = rows[(i0 + lane) * RSTR + widx];
            unsigned ext = __shfl_sync(0xffffffffu, supp, widx);
            unsigned sw = ext | ~vmask;
            unsigned keep = 0;
            #pragma unroll
            for (int t = 0; t < 32; ++t) {
                unsigned dt = __shfl_sync(0xffffffffu, dw, t);
                if (!((sw >> t) & 1u)) { sw |= dt; keep |= (1u << t); }
            }
            unsigned acc = 0;
            #pragma unroll
            for (int t = 0; t < 32; ++t)
                if ((keep >> t) & 1u) acc |= rows[(i0 + t) * RSTR + lane];
            supp |= acc;
            if (lane == 0) keepw[widx] = keep;
        }
    }
    __syncthreads();

    // output
    if (tid < TOPK) {
        bool keep = (keepw[tid >> 5] >> (tid & 31)) & 1u;
        float4 bx = boxp[tid];
        float so  = score[tid];
        float cf  = clsf[tid];
        if (!keep) { bx = make_float4(0.f, 0.f, 0.f, 0.f); so = 0.f; cf = 0.f; }
        float* o = out + ((size_t)b * TOPK + tid) * 6;
        o[0] = bx.x; o[1] = bx.y; o[2] = bx.z; o[3] = bx.w; o[4] = so; o[5] = cf;
    }
    if (tid == 0) g_scnt[b] = 0u;   // self-clean
}

// ---------------- launcher ----------------
extern "C" void kernel_launch(void* const* d_in, const int* in_sizes, int n_in,
                              void* d_out, int out_size) {
    (void)in_sizes; (void)n_in; (void)out_size;
    const float* x = (const float*)d_in[0];
    float* out = (float*)d_out;
    cudaFuncSetAttribute(k_sel,  cudaFuncAttributeMaxDynamicSharedMemorySize, SEL_SMEM);
    cudaFuncSetAttribute(k_post, cudaFuncAttributeMaxDynamicSharedMemorySize, K3_SMEM);

    k_score<<<(BATCH * NANCH) / SB, SB>>>(x);
    k_pick <<<BATCH, 1024>>>();
    k_cand <<<dim3(25, BATCH), 1024>>>();
    k_sel  <<<BATCH, 1024, SEL_SMEM>>>();
    k_coll <<<dim3(25, BATCH), 1024>>>();
    k_post <<<BATCH, 1024, K3_SMEM>>>(x, out);
}

// round 11
// speedup vs baseline: 1.0040x; 1.0040x over previous
#include <cuda_runtime.h>
#include <cstdint>

#define BATCH   8
#define NANCH   25200
#define NCH     85
#define TOPK    1000
#define KPAD    1024
#define NCLS    80
#define CONF_TH 0.25f
#define IOU_TH  0.45f
#define MAX_WH  4096.0f
#define NB14    16384
#define CAP     8192
#define RSTR    33

// ---------------- scratch (device globals; no allocation) ----------------
__device__ unsigned           g_enc [BATCH * NANCH];
__device__ unsigned           g_hist[BATCH * NB14];   // zeroed by k_pick after use
__device__ unsigned long long g_cand[BATCH * CAP];
__device__ unsigned           g_ccnt[BATCH];          // zeroed by k_post after use
__device__ unsigned           g_bucket[BATCH];
__device__ unsigned           g_need[BATCH];
__device__ unsigned long long g_T64[BATCH];           // 0 = needs rank step

// ---------------- K1: score = obj * max(cls); encode; fused 14-bit histogram ----------------
#define SB 128
__global__ void __launch_bounds__(SB) k_score(const float* __restrict__ x) {
    __shared__ float sx[SB * NCH];   // 43520 B
    const int tid = threadIdx.x;
    const size_t base = (size_t)blockIdx.x * SB * NCH;
    const float4* xv = (const float4*)(x + base);
    float4* sv = (float4*)sx;
    #pragma unroll
    for (int t = tid; t < SB * NCH / 4; t += SB) sv[t] = xv[t];
    __syncthreads();

    const int a = blockIdx.x * SB + tid;
    const float* p = sx + tid * NCH;
    const float obj = p[4];

    // max over p[5..85): peel to 16B alignment, then 4-wide fmax tree (ILP=4)
    const int off = tid * NCH + 5;
    const int pre = (-off) & 3;                  // 0..3 scalars before alignment
    float m0 = __int_as_float(0xff800000);       // -inf
    for (int k = 0; k < pre; ++k) m0 = fmaxf(m0, sx[off + k]);
    const int a0  = off + pre;
    const int n   = 80 - pre;
    const int nf4 = n >> 2;
    const int tl  = n & 3;
    const float4* pv = (const float4*)(sx + a0);
    float4 acc = pv[0];
    #pragma unroll 4
    for (int q = 1; q < nf4; ++q) {
        float4 v = pv[q];
        acc.x = fmaxf(acc.x, v.x); acc.y = fmaxf(acc.y, v.y);
        acc.z = fmaxf(acc.z, v.z); acc.w = fmaxf(acc.w, v.w);
    }
    float m = fmaxf(fmaxf(acc.x, acc.y), fmaxf(acc.z, acc.w));
    m = fmaxf(m, m0);
    const int tb = a0 + 4 * nf4;
    for (int k = 0; k < tl; ++k) m = fmaxf(m, sx[tb + k]);

    float sc = __fmul_rn(obj, m);
    unsigned u = __float_as_uint((sc > CONF_TH) ? sc : -1.0f);
    unsigned e = (u & 0x80000000u) ? ~u : (u | 0x80000000u);
    g_enc[a] = e;

    int b = a / NANCH;
    unsigned addr = (unsigned)b * NB14 + (e >> 18);
    unsigned mm = __match_any_sync(0xffffffffu, addr);
    if ((tid & 31) == (__ffs(mm) - 1))
        atomicAdd(&g_hist[addr], (unsigned)__popc(mm));
}

// ---------------- K2a: boundary bucket via register suffix scan (no smem hist) ----------------
__global__ void __launch_bounds__(1024) k_pick() {
    const int b = blockIdx.x, tid = threadIdx.x;
    const int wid = tid >> 5, lane = tid & 31;
    __shared__ unsigned s_w[32];

    // 16 buckets per thread, read coalesced as 4x uint4 (64B-aligned)
    unsigned lv[16];
    const uint4* hv = (const uint4*)(g_hist + b * NB14 + tid * 16);
    #pragma unroll
    for (int q = 0; q < 4; ++q) {
        uint4 h = hv[q];
        lv[q * 4 + 0] = h.x; lv[q * 4 + 1] = h.y;
        lv[q * 4 + 2] = h.z; lv[q * 4 + 3] = h.w;
    }
    // coalesced self-clean
    uint4* hz = (uint4*)(g_hist + b * NB14 + tid * 16);
    const uint4 z4 = make_uint4(0u, 0u, 0u, 0u);
    #pragma unroll
    for (int q = 0; q < 4; ++q) hz[q] = z4;

    unsigned run = 0;
    #pragma unroll
    for (int i = 15; i >= 0; --i) { run += lv[i]; lv[i] = run; }   // local inclusive suffix
    const unsigned ttot = run;
    unsigned v = ttot;
    #pragma unroll
    for (int off = 1; off < 32; off <<= 1) {
        unsigned t = __shfl_down_sync(0xffffffffu, v, off);
        if (lane + off < 32) v += t;
    }
    if (lane == 0) s_w[wid] = v;          // warp totals
    __syncthreads();
    if (tid < 32) {
        unsigned u0 = s_w[tid], w = u0;
        #pragma unroll
        for (int off = 1; off < 32; off <<= 1) {
            unsigned t = __shfl_down_sync(0xffffffffu, w, off);
            if (tid + off < 32) w += t;
        }
        s_w[tid] = w - u0;                // exclusive suffix over higher warps
    }
    __syncthreads();
    {
        const int base16 = tid * 16;
        unsigned above = s_w[wid] + (v - ttot);
        #pragma unroll
        for (int i = 0; i < 16; ++i) {
            unsigned tot = above + lv[i];
            unsigned cnt = lv[i] - ((i < 15) ? lv[i + 1] : 0u);
            unsigned gt  = tot - cnt;
            if (gt < TOPK && TOPK <= tot) {
                unsigned need = TOPK - gt;
                g_bucket[b] = (unsigned)(base16 + i);
                g_need[b]   = need;
                g_T64[b]    = (need == cnt)
                              ? ((unsigned long long)(base16 + i) << 50) : 0ull;
            }
        }
    }
}

// ---------------- K2b: compact boundary-bucket candidates (grid-wide) ----------------
__global__ void __launch_bounds__(1024) k_cand() {
    const int b = blockIdx.y;
    const int i = blockIdx.x * 1024 + threadIdx.x;
    if (i >= NANCH) return;
    unsigned e = g_enc[b * NANCH + i];
    if ((e >> 18) == g_bucket[b]) {
        unsigned pos = atomicAdd(&g_ccnt[b], 1u);
        if (pos < CAP)
            g_cand[b * CAP + pos] =
                ((unsigned long long)e << 32) | (unsigned)(~(unsigned)i);
    }
}

// ---------------- K3: rank + collect + sort + gather + sparse IoU + scan + output ----------------
#define PO_ROWS   0
#define PO_BOXO   135168
#define PO_BOXP   151552
#define PO_AREA   167936
#define PO_SCORE  172032
#define PO_CLSF   176128
#define PO_CLIST  180224
#define PO_CBASE  184320
#define PO_COFF   184832
#define PO_KEEPW  185344
#define PO_OUTK   185472
#define K3_SMEM   193664
// aliases inside rows region (used before rows is zeroed):
#define AL_CAND   0        // u64[CAP] = 64KB
#define AL_HIST2  65536    // u32[2048]
#define AL_SCN2   73728    // u32[2048]

__global__ void __launch_bounds__(1024) k_post(const float* __restrict__ x,
                                               float* __restrict__ out) {
    const int b   = blockIdx.x;
    const int tid = threadIdx.x;
    const int lane = tid & 31;
    extern __shared__ unsigned char sm[];
    unsigned* rows  = (unsigned*)(sm + PO_ROWS);
    float4*   boxo  = (float4*)  (sm + PO_BOXO);
    float4*   boxp  = (float4*)  (sm + PO_BOXP);
    float*    area  = (float*)   (sm + PO_AREA);
    float*    score = (float*)   (sm + PO_SCORE);
    float*    clsf  = (float*)   (sm + PO_CLSF);
    int*      clist = (int*)     (sm + PO_CLIST);
    int*      cbase = (int*)     (sm + PO_CBASE);
    int*      coff  = (int*)     (sm + PO_COFF);
    unsigned* keepw = (unsigned*)(sm + PO_KEEPW);
    unsigned long long* outk  = (unsigned long long*)(sm + PO_OUTK);
    unsigned long long* cand  = (unsigned long long*)(sm + AL_CAND);
    unsigned*           hist2 = (unsigned*)(sm + AL_HIST2);
    unsigned*           scn2  = (unsigned*)(sm + AL_SCN2);
    __shared__ unsigned s_ctrl[4];
    __shared__ unsigned long long s_T64;

    const unsigned* encb = g_enc + b * NANCH;

    // ---- Phase 1: exact 1000th key T64 (rank-by-count over boundary bucket) ----
    unsigned long long T64 = g_T64[b];
    if (T64 == 0ull) {
        unsigned M0 = g_ccnt[b];
        unsigned need = g_need[b];
        unsigned C;
        if (M0 <= CAP) {
            C = M0;
            for (unsigned j = tid; j < C; j += 1024) cand[j] = g_cand[b * CAP + j];
            __syncthreads();
        } else {
            // rare: refine bucket over g_enc until candidates fit CAP, then compact
            unsigned long long prefix = (unsigned long long)g_bucket[b];
            int shift = 50;
            unsigned count = M0;
            while (count > CAP) {
                int w = (shift >= 11) ? 11 : shift;
                int s2 = shift - w;
                unsigned dmask = (1u << w) - 1u;
                for (int t = tid; t < 2048; t += 1024) hist2[t] = 0u;
                __syncthreads();
                for (int it = 0; it < 25; ++it) {
                    int i = tid + it * 1024;
                    if (i < NANCH) {
                        unsigned long long key =
                            ((unsigned long long)encb[i] << 32) | (unsigned)(~(unsigned)i);
                        if ((key >> shift) == prefix)
                            atomicAdd(&hist2[(unsigned)((key >> s2) & dmask)], 1u);
                    }
                }
                __syncthreads();
                for (int t = tid; t < 2048; t += 1024) scn2[t] = hist2[t];
                __syncthreads();
                for (int d = 1; d < 2048; d <<= 1) {
                    unsigned a0 = (tid + d < 2048) ? scn2[tid + d] : 0u;
                    unsigned a1 = (tid + 1024 + d < 2048) ? scn2[tid + 1024 + d] : 0u;
                    __syncthreads();
                    scn2[tid] += a0; scn2[tid + 1024] += a1;
                    __syncthreads();
                }
                #pragma unroll
                for (int q = 0; q < 2; ++q) {
                    int d = tid + q * 1024;
                    unsigned tot = scn2[d], gt = tot - hist2[d];
                    if (gt < need && need <= tot) {
                        s_ctrl[0] = (unsigned)d;
                        s_ctrl[1] = need - gt;
                        s_ctrl[2] = hist2[d];
                    }
                }
                __syncthreads();
                prefix = (prefix << w) | (unsigned long long)s_ctrl[0];
                need = s_ctrl[1]; count = s_ctrl[2]; shift = s2;
                __syncthreads();
            }
            if (tid == 0) s_ctrl[3] = 0u;
            __syncthreads();
            for (int it = 0; it < 25; ++it) {
                int i = tid + it * 1024;
                if (i < NANCH) {
                    unsigned long long key =
                        ((unsigned long long)encb[i] << 32) | (unsigned)(~(unsigned)i);
                    if ((key >> shift) == prefix) {
                        unsigned pos = atomicAdd(&s_ctrl[3], 1u);
                        if (pos < CAP) cand[pos] = key;
                    }
                }
            }
            __syncthreads();
            C = s_ctrl[3];
        }
        // rank-by-count: key with exactly (need-1) greater keys
        for (unsigned j = tid; j < C; j += 1024) {
            unsigned long long kj = cand[j];
            unsigned gt = 0;
            for (unsigned k = 0; k < C; ++k) gt += (cand[k] > kj);
            if (gt == need - 1) s_T64 = kj;
        }
        __syncthreads();
        T64 = s_T64;
    }

    // ---- Phase 2: collect the exactly-1000 keys >= T64 (unrolled for MLP) ----
    if (tid == 0) s_ctrl[3] = 0u;
    __syncthreads();
    #pragma unroll 5
    for (int it = 0; it < 25; ++it) {
        int i = tid + it * 1024;
        if (i < NANCH) {
            unsigned long long key =
                ((unsigned long long)encb[i] << 32) | (unsigned)(~(unsigned)i);
            if (key >= T64) {
                unsigned pos = atomicAdd(&s_ctrl[3], 1u);
                if (pos < KPAD) outk[pos] = key;
            }
        }
    }
    __syncthreads();
    const unsigned ncol = (s_ctrl[3] < KPAD) ? s_ctrl[3] : KPAD;
    if (tid >= (int)ncol) outk[tid] = 0ull;
    __syncthreads();

    // ---- Phase 3: bitonic sort 1024 desc (distinct keys; zeros sink) ----
    for (unsigned kk = 2; kk <= 1024; kk <<= 1) {
        for (unsigned j = kk >> 1; j > 0; j >>= 1) {
            unsigned i = (unsigned)tid, ixj = i ^ j;
            if (ixj > i) {
                unsigned long long a = outk[i], bb = outk[ixj];
                bool desc = ((i & kk) == 0);
                if (desc ? (a < bb) : (a > bb)) { outk[i] = bb; outk[ixj] = a; }
            }
            __syncthreads();
        }
    }

    // ---- Phase 4: zero bitmat; decode + gather + argmax for the 1000 winners ----
    for (int t = tid; t < KPAD * RSTR; t += 1024) rows[t] = 0u;
    if (tid < NCLS) coff[tid] = 0;
    if (tid < 32)   keepw[tid] = 0u;

    unsigned long long key = outk[tid];
    float sc = -1.0f;
    int   idx = 0;
    if (key != 0ull) {
        unsigned e = (unsigned)(key >> 32);
        unsigned u = (e & 0x80000000u) ? (e ^ 0x80000000u) : ~e;
        sc = __uint_as_float(u);
        idx = (int)(~(unsigned)(key & 0xffffffffull));
    }
    score[tid] = sc;
    int c = -1;
    if (tid < TOPK && key != 0ull) {
        const float* p = x + ((size_t)b * NANCH + idx) * NCH;
        float cx = p[0], cy = p[1], w = p[2], h = p[3];
        float best = p[5]; int bi = 0;
        #pragma unroll 8
        for (int cc = 1; cc < NCLS; ++cc) {
            float vv = p[5 + cc];
            if (vv > best) { best = vv; bi = cc; }   // strict >: lowest index on ties
        }
        c = bi;
        float hw = __fmul_rn(w, 0.5f), hh = __fmul_rn(h, 0.5f);
        float x1 = __fsub_rn(cx, hw), y1 = __fsub_rn(cy, hh);
        float x2 = __fadd_rn(cx, hw), y2 = __fadd_rn(cy, hh);
        float cf = (float)c;
        float o  = __fmul_rn(cf, MAX_WH);
        float ox1 = __fadd_rn(x1, o), oy1 = __fadd_rn(y1, o);
        float ox2 = __fadd_rn(x2, o), oy2 = __fadd_rn(y2, o);
        boxp[tid] = make_float4(x1, y1, x2, y2);
        boxo[tid] = make_float4(ox1, oy1, ox2, oy2);
        area[tid] = __fmul_rn(__fsub_rn(ox2, ox1), __fsub_rn(oy2, oy1));
        clsf[tid] = cf;
    } else {
        boxp[tid] = make_float4(0.f, 0.f, 0.f, 0.f);
        boxo[tid] = make_float4(0.f, 0.f, 0.f, 0.f);
        area[tid] = 0.f; clsf[tid] = 0.f;
    }
    int V = __syncthreads_count(tid < TOPK && sc > CONF_TH);

    // ---- Phase 5: counting sort by class (cross-class IoU exactly 0) ----
    if (c >= 0) atomicAdd(&coff[c], 1);
    __syncthreads();
    if (tid == 0) {
        int r2 = 0;
        #pragma unroll
        for (int k = 0; k < NCLS; ++k) { cbase[k] = r2; r2 += coff[k]; }
        cbase[NCLS] = r2;
    }
    __syncthreads();
    if (tid < NCLS) coff[tid] = cbase[tid];
    __syncthreads();
    if (c >= 0) clist[atomicAdd(&coff[c], 1)] = tid;
    __syncthreads();

    // ---- Phase 6: sparse IoU (reference fp32 arithmetic, FMA-free) ----
    if (c >= 0) {
        float4 bi4 = boxo[tid];
        float  ai  = area[tid];
        int k0 = cbase[c], k1 = cbase[c + 1];
        for (int k = k0; k < k1; ++k) {
            int j = clist[k];
            if (j == tid) continue;
            float4 bj = boxo[j];
            float ww = fmaxf(__fsub_rn(fminf(bi4.z, bj.z), fmaxf(bi4.x, bj.x)), 0.0f);
            float hh = fmaxf(__fsub_rn(fminf(bi4.w, bj.w), fmaxf(bi4.y, bj.y)), 0.0f);
            float inter = __fmul_rn(ww, hh);
            float den = __fadd_rn(__fsub_rn(__fadd_rn(ai, area[j]), inter), 1e-9f);
            if (__fdiv_rn(inter, den) > IOU_TH)
                rows[tid * RSTR + (j >> 5)] |= (1u << (j & 31));
        }
    }
    __syncthreads();

    // ---- Phase 7: windowed greedy scan (warp 0) ----
    if (tid < 32) {
        int nwin = (V + 31) >> 5;
        unsigned supp = 0;
        for (int widx = 0; widx < nwin; ++widx) {
            int i0 = widx << 5;
            int lim = V - i0;
            unsigned vmask = (lim >= 32) ? 0xffffffffu : ((1u << lim) - 1u);
            unsigned dw = rows[(i0 + lane) * RSTR + widx];
            unsigned ext = __shfl_sync(0xffffffffu, supp, widx);
            unsigned sw = ext | ~vmask;
            unsigned keep = 0;
            #pragma unroll
            for (int t = 0; t < 32; ++t) {
                unsigned dt = __shfl_sync(0xffffffffu, dw, t);
                if (!((sw >> t) & 1u)) { sw |= dt; keep |= (1u << t); }
            }
            unsigned acc = 0;
            #pragma unroll
            for (int t = 0; t < 32; ++t)
                if ((keep >> t) & 1u) acc |= rows[(i0 + t) * RSTR + lane];
            supp |= acc;
            if (lane == 0) keepw[widx] = keep;
        }
    }
    __syncthreads();

    // ---- Phase 8: output + self-clean ----
    if (tid < TOPK) {
        bool keep = (keepw[tid >> 5] >> (tid & 31)) & 1u;
        float4 bx = boxp[tid];
        float so  = score[tid];
        float cf  = clsf[tid];
        if (!keep) { bx = make_float4(0.f, 0.f, 0.f, 0.f); so = 0.f; cf = 0.f; }
        float* o = out + ((size_t)b * TOPK + tid) * 6;
        o[0] = bx.x; o[1] = bx.y; o[2] = bx.z; o[3] = bx.w; o[4] = so; o[5] = cf;
    }
    if (tid == 0) g_ccnt[b] = 0u;   // ready for next replay
}

// ---------------- launcher ----------------
extern "C" void kernel_launch(void* const* d_in, const int* in_sizes, int n_in,
                              void* d_out, int out_size) {
    (void)in_sizes; (void)n_in; (void)out_size;
    const float* x = (const float*)d_in[0];
    float* out = (float*)d_out;
    cudaFuncSetAttribute(k_post, cudaFuncAttributeMaxDynamicSharedMemorySize, K3_SMEM);

    k_score<<<(BATCH * NANCH) / SB, SB>>>(x);
    k_pick <<<BATCH, 1024>>>();
    k_cand <<<dim3(25, BATCH), 1024>>>();
    k_post <<<BATCH, 1024, K3_SMEM>>>(x, out);
}

// round 12
// speedup vs baseline: 1.2238x; 1.2190x over previous
#include <cuda_runtime.h>
#include <cstdint>

#define BATCH   8
#define NANCH   25200
#define NCH     85
#define TOPK    1000
#define KPAD    1024
#define NCLS    80
#define CONF_TH 0.25f
#define IOU_TH  0.45f
#define MAX_WH  4096.0f
#define NB14    16384
#define CAP     8192
#define RSTR    33

// ---------------- scratch (device globals; no allocation) ----------------
__device__ unsigned           g_enc [BATCH * NANCH];
__device__ unsigned           g_hist[BATCH * NB14];   // zeroed by k_pick after use
__device__ unsigned long long g_cand[BATCH * CAP];
__device__ unsigned           g_ccnt[BATCH];          // zeroed by k_post after use
__device__ unsigned           g_bucket[BATCH];
__device__ unsigned           g_need[BATCH];
__device__ unsigned long long g_T64[BATCH];           // 0 = needs rank step

// ---------------- K1: score = obj * max(cls); encode; fused 14-bit histogram ----------------
#define SB 128
__global__ void __launch_bounds__(SB) k_score(const float* __restrict__ x) {
    __shared__ float sx[SB * NCH];   // 43520 B
    const int tid = threadIdx.x;
    const size_t base = (size_t)blockIdx.x * SB * NCH;
    const float4* xv = (const float4*)(x + base);
    float4* sv = (float4*)sx;
    #pragma unroll
    for (int t = tid; t < SB * NCH / 4; t += SB) sv[t] = xv[t];
    __syncthreads();

    const int a = blockIdx.x * SB + tid;
    const float* p = sx + tid * NCH;
    const float obj = p[4];

    // max over p[5..85): peel to 16B alignment, then 4-wide fmax tree (ILP=4)
    const int off = tid * NCH + 5;
    const int pre = (-off) & 3;
    float m0 = __int_as_float(0xff800000);       // -inf
    for (int k = 0; k < pre; ++k) m0 = fmaxf(m0, sx[off + k]);
    const int a0  = off + pre;
    const int n   = 80 - pre;
    const int nf4 = n >> 2;
    const int tl  = n & 3;
    const float4* pv = (const float4*)(sx + a0);
    float4 acc = pv[0];
    #pragma unroll 4
    for (int q = 1; q < nf4; ++q) {
        float4 v = pv[q];
        acc.x = fmaxf(acc.x, v.x); acc.y = fmaxf(acc.y, v.y);
        acc.z = fmaxf(acc.z, v.z); acc.w = fmaxf(acc.w, v.w);
    }
    float m = fmaxf(fmaxf(acc.x, acc.y), fmaxf(acc.z, acc.w));
    m = fmaxf(m, m0);
    const int tb = a0 + 4 * nf4;
    for (int k = 0; k < tl; ++k) m = fmaxf(m, sx[tb + k]);

    float sc = __fmul_rn(obj, m);
    unsigned u = __float_as_uint((sc > CONF_TH) ? sc : -1.0f);
    unsigned e = (u & 0x80000000u) ? ~u : (u | 0x80000000u);
    g_enc[a] = e;

    int b = a / NANCH;
    unsigned addr = (unsigned)b * NB14 + (e >> 18);
    unsigned mm = __match_any_sync(0xffffffffu, addr);
    if ((tid & 31) == (__ffs(mm) - 1))
        atomicAdd(&g_hist[addr], (unsigned)__popc(mm));
}

// ---------------- K2a: boundary bucket via register suffix scan ----------------
__global__ void __launch_bounds__(1024) k_pick() {
    const int b = blockIdx.x, tid = threadIdx.x;
    const int wid = tid >> 5, lane = tid & 31;
    __shared__ unsigned s_w[32];

    unsigned lv[16];
    const uint4* hv = (const uint4*)(g_hist + b * NB14 + tid * 16);
    #pragma unroll
    for (int q = 0; q < 4; ++q) {
        uint4 h = hv[q];
        lv[q * 4 + 0] = h.x; lv[q * 4 + 1] = h.y;
        lv[q * 4 + 2] = h.z; lv[q * 4 + 3] = h.w;
    }
    uint4* hz = (uint4*)(g_hist + b * NB14 + tid * 16);
    const uint4 z4 = make_uint4(0u, 0u, 0u, 0u);
    #pragma unroll
    for (int q = 0; q < 4; ++q) hz[q] = z4;

    unsigned run = 0;
    #pragma unroll
    for (int i = 15; i >= 0; --i) { run += lv[i]; lv[i] = run; }
    const unsigned ttot = run;
    unsigned v = ttot;
    #pragma unroll
    for (int off = 1; off < 32; off <<= 1) {
        unsigned t = __shfl_down_sync(0xffffffffu, v, off);
        if (lane + off < 32) v += t;
    }
    if (lane == 0) s_w[wid] = v;
    __syncthreads();
    if (tid < 32) {
        unsigned u0 = s_w[tid], w = u0;
        #pragma unroll
        for (int off = 1; off < 32; off <<= 1) {
            unsigned t = __shfl_down_sync(0xffffffffu, w, off);
            if (tid + off < 32) w += t;
        }
        s_w[tid] = w - u0;
    }
    __syncthreads();
    {
        const int base16 = tid * 16;
        unsigned above = s_w[wid] + (v - ttot);
        #pragma unroll
        for (int i = 0; i < 16; ++i) {
            unsigned tot = above + lv[i];
            unsigned cnt = lv[i] - ((i < 15) ? lv[i + 1] : 0u);
            unsigned gt  = tot - cnt;
            if (gt < TOPK && TOPK <= tot) {
                unsigned need = TOPK - gt;
                g_bucket[b] = (unsigned)(base16 + i);
                g_need[b]   = need;
                g_T64[b]    = (need == cnt)
                              ? ((unsigned long long)(base16 + i) << 50) : 0ull;
            }
        }
    }
}

// ---------------- K2b: compact boundary-bucket candidates (grid-wide) ----------------
__global__ void __launch_bounds__(1024) k_cand() {
    const int b = blockIdx.y;
    const int i = blockIdx.x * 1024 + threadIdx.x;
    if (i >= NANCH) return;
    unsigned e = g_enc[b * NANCH + i];
    if ((e >> 18) == g_bucket[b]) {
        unsigned pos = atomicAdd(&g_ccnt[b], 1u);
        if (pos < CAP)
            g_cand[b * CAP + pos] =
                ((unsigned long long)e << 32) | (unsigned)(~(unsigned)i);
    }
}

// ---------------- K3: rank + collect + sort + gather + sparse IoU + scan + output ----------------
#define PO_ROWS   0
#define PO_BOXO   135168
#define PO_BOXP   151552
#define PO_AREA   167936
#define PO_SCORE  172032
#define PO_CLSF   176128
#define PO_CLIST  180224
#define PO_CBASE  184320
#define PO_COFF   184832
#define PO_KEEPW  185344
#define PO_OUTK   185472
#define PO_SIDX   193664
#define PO_SCLS   197760
#define K3_SMEM   201856
// aliases inside rows region (used before rows is zeroed):
#define AL_CAND   0        // u64[CAP] = 64KB
#define AL_HIST2  65536    // u32[2048]
#define AL_SCN2   73728    // u32[2048]

__global__ void __launch_bounds__(1024) k_post(const float* __restrict__ x,
                                               float* __restrict__ out) {
    const int b   = blockIdx.x;
    const int tid = threadIdx.x;
    const int wid = tid >> 5, lane = tid & 31;
    extern __shared__ unsigned char sm[];
    unsigned* rows  = (unsigned*)(sm + PO_ROWS);
    float4*   boxo  = (float4*)  (sm + PO_BOXO);
    float4*   boxp  = (float4*)  (sm + PO_BOXP);
    float*    area  = (float*)   (sm + PO_AREA);
    float*    score = (float*)   (sm + PO_SCORE);
    float*    clsf  = (float*)   (sm + PO_CLSF);
    int*      clist = (int*)     (sm + PO_CLIST);
    int*      cbase = (int*)     (sm + PO_CBASE);
    int*      coff  = (int*)     (sm + PO_COFF);
    unsigned* keepw = (unsigned*)(sm + PO_KEEPW);
    unsigned long long* outk  = (unsigned long long*)(sm + PO_OUTK);
    int*      sidx  = (int*)     (sm + PO_SIDX);
    int*      scls  = (int*)     (sm + PO_SCLS);
    unsigned long long* cand  = (unsigned long long*)(sm + AL_CAND);
    unsigned*           hist2 = (unsigned*)(sm + AL_HIST2);
    unsigned*           scn2  = (unsigned*)(sm + AL_SCN2);
    __shared__ unsigned s_ctrl[4];
    __shared__ unsigned long long s_T64;

    const unsigned* encb = g_enc + b * NANCH;

    // ---- Phase 1: exact 1000th key T64 (rank-by-count over boundary bucket) ----
    unsigned long long T64 = g_T64[b];
    if (T64 == 0ull) {
        unsigned M0 = g_ccnt[b];
        unsigned need = g_need[b];
        unsigned C;
        if (M0 <= CAP) {
            C = M0;
            for (unsigned j = tid; j < C; j += 1024) cand[j] = g_cand[b * CAP + j];
            __syncthreads();
        } else {
            // rare: refine bucket over g_enc until candidates fit CAP, then compact
            unsigned long long prefix = (unsigned long long)g_bucket[b];
            int shift = 50;
            unsigned count = M0;
            while (count > CAP) {
                int w = (shift >= 11) ? 11 : shift;
                int s2 = shift - w;
                unsigned dmask = (1u << w) - 1u;
                for (int t = tid; t < 2048; t += 1024) hist2[t] = 0u;
                __syncthreads();
                for (int it = 0; it < 25; ++it) {
                    int i = tid + it * 1024;
                    if (i < NANCH) {
                        unsigned long long key =
                            ((unsigned long long)encb[i] << 32) | (unsigned)(~(unsigned)i);
                        if ((key >> shift) == prefix)
                            atomicAdd(&hist2[(unsigned)((key >> s2) & dmask)], 1u);
                    }
                }
                __syncthreads();
                for (int t = tid; t < 2048; t += 1024) scn2[t] = hist2[t];
                __syncthreads();
                for (int d = 1; d < 2048; d <<= 1) {
                    unsigned a0 = (tid + d < 2048) ? scn2[tid + d] : 0u;
                    unsigned a1 = (tid + 1024 + d < 2048) ? scn2[tid + 1024 + d] : 0u;
                    __syncthreads();
                    scn2[tid] += a0; scn2[tid + 1024] += a1;
                    __syncthreads();
                }
                #pragma unroll
                for (int q = 0; q < 2; ++q) {
                    int d = tid + q * 1024;
                    unsigned tot = scn2[d], gt = tot - hist2[d];
                    if (gt < need && need <= tot) {
                        s_ctrl[0] = (unsigned)d;
                        s_ctrl[1] = need - gt;
                        s_ctrl[2] = hist2[d];
                    }
                }
                __syncthreads();
                prefix = (prefix << w) | (unsigned long long)s_ctrl[0];
                need = s_ctrl[1]; count = s_ctrl[2]; shift = s2;
                __syncthreads();
            }
            if (tid == 0) s_ctrl[3] = 0u;
            __syncthreads();
            for (int it = 0; it < 25; ++it) {
                int i = tid + it * 1024;
                if (i < NANCH) {
                    unsigned long long key =
                        ((unsigned long long)encb[i] << 32) | (unsigned)(~(unsigned)i);
                    if ((key >> shift) == prefix) {
                        unsigned pos = atomicAdd(&s_ctrl[3], 1u);
                        if (pos < CAP) cand[pos] = key;
                    }
                }
            }
            __syncthreads();
            C = s_ctrl[3];
        }
        for (unsigned j = tid; j < C; j += 1024) {
            unsigned long long kj = cand[j];
            unsigned gt = 0;
            for (unsigned k = 0; k < C; ++k) gt += (cand[k] > kj);
            if (gt == need - 1) s_T64 = kj;
        }
        __syncthreads();
        T64 = s_T64;
    }

    // ---- Phase 2: collect the exactly-1000 keys >= T64 ----
    if (tid == 0) s_ctrl[3] = 0u;
    __syncthreads();
    #pragma unroll 5
    for (int it = 0; it < 25; ++it) {
        int i = tid + it * 1024;
        if (i < NANCH) {
            unsigned long long key =
                ((unsigned long long)encb[i] << 32) | (unsigned)(~(unsigned)i);
            if (key >= T64) {
                unsigned pos = atomicAdd(&s_ctrl[3], 1u);
                if (pos < KPAD) outk[pos] = key;
            }
        }
    }
    __syncthreads();
    const unsigned ncol = (s_ctrl[3] < KPAD) ? s_ctrl[3] : KPAD;
    if (tid >= (int)ncol) outk[tid] = 0ull;
    __syncthreads();

    // ---- Phase 3: bitonic sort 1024 desc (distinct keys; zeros sink) ----
    for (unsigned kk = 2; kk <= 1024; kk <<= 1) {
        for (unsigned j = kk >> 1; j > 0; j >>= 1) {
            unsigned i = (unsigned)tid, ixj = i ^ j;
            if (ixj > i) {
                unsigned long long a = outk[i], bb = outk[ixj];
                bool desc = ((i & kk) == 0);
                if (desc ? (a < bb) : (a > bb)) { outk[i] = bb; outk[ixj] = a; }
            }
            __syncthreads();
        }
    }

    // ---- Phase 4: zero bitmat; decode; warp-per-row coalesced gather + argmax ----
    for (int t = tid; t < KPAD * RSTR; t += 1024) rows[t] = 0u;
    if (tid < NCLS) coff[tid] = 0;
    if (tid < 32)   keepw[tid] = 0u;

    unsigned long long key = outk[tid];
    float sc = -1.0f;
    int   idx = -1;
    if (key != 0ull) {
        unsigned e = (unsigned)(key >> 32);
        unsigned u = (e & 0x80000000u) ? (e ^ 0x80000000u) : ~e;
        sc = __uint_as_float(u);
        idx = (int)(~(unsigned)(key & 0xffffffffull));
    }
    score[tid] = sc;
    sidx[tid]  = (tid < TOPK) ? idx : -1;
    scls[tid]  = -1;
    boxp[tid] = make_float4(0.f, 0.f, 0.f, 0.f);
    boxo[tid] = make_float4(0.f, 0.f, 0.f, 0.f);
    area[tid] = 0.f; clsf[tid] = 0.f;
    __syncthreads();

    // one warp per winner row: coalesced 85-float load + shuffle argmax (tie -> lowest class)
    for (int r = wid; r < TOPK; r += 32) {
        int idr = sidx[r];
        if (idr < 0) continue;
        const float* p = x + ((size_t)b * NANCH + idr) * NCH;
        float v0 = p[lane];
        float v1 = p[32 + lane];
        float v2 = (lane < 21) ? p[64 + lane] : 0.0f;
        float best = __int_as_float(0xff800000);
        int   bi   = 1 << 30;
        if (lane >= 5)              { best = v0; bi = lane - 5;  }   // cls 0..26
        if (v1 > best)              { best = v1; bi = 27 + lane; }   // cls 27..58
        if (lane < 21 && v2 > best) { best = v2; bi = 59 + lane; }   // cls 59..79
        #pragma unroll
        for (int o = 16; o; o >>= 1) {
            float ov = __shfl_down_sync(0xffffffffu, best, o);
            int   oi = __shfl_down_sync(0xffffffffu, bi, o);
            if (ov > best || (ov == best && oi < bi)) { best = ov; bi = oi; }
        }
        float cx = __shfl_sync(0xffffffffu, v0, 0);
        float cy = __shfl_sync(0xffffffffu, v0, 1);
        float w  = __shfl_sync(0xffffffffu, v0, 2);
        float h  = __shfl_sync(0xffffffffu, v0, 3);
        if (lane == 0) {
            float hw = __fmul_rn(w, 0.5f), hh = __fmul_rn(h, 0.5f);
            float x1 = __fsub_rn(cx, hw), y1 = __fsub_rn(cy, hh);
            float x2 = __fadd_rn(cx, hw), y2 = __fadd_rn(cy, hh);
            float cf = (float)bi;
            float o2 = __fmul_rn(cf, MAX_WH);
            float ox1 = __fadd_rn(x1, o2), oy1 = __fadd_rn(y1, o2);
            float ox2 = __fadd_rn(x2, o2), oy2 = __fadd_rn(y2, o2);
            boxp[r] = make_float4(x1, y1, x2, y2);
            boxo[r] = make_float4(ox1, oy1, ox2, oy2);
            area[r] = __fmul_rn(__fsub_rn(ox2, ox1), __fsub_rn(oy2, oy1));
            clsf[r] = cf;
            scls[r] = bi;
        }
    }
    __syncthreads();
    const int c = scls[tid];
    int V = __syncthreads_count(tid < TOPK && score[tid] > CONF_TH);

    // ---- Phase 5: counting sort by class (cross-class IoU exactly 0) ----
    if (c >= 0) atomicAdd(&coff[c], 1);
    __syncthreads();
    if (tid == 0) {
        int r2 = 0;
        #pragma unroll
        for (int k = 0; k < NCLS; ++k) { cbase[k] = r2; r2 += coff[k]; }
        cbase[NCLS] = r2;
    }
    __syncthreads();
    if (tid < NCLS) coff[tid] = cbase[tid];
    __syncthreads();
    if (c >= 0) clist[atomicAdd(&coff[c], 1)] = tid;
    __syncthreads();

    // ---- Phase 6: sparse IoU (reference fp32 arithmetic, FMA-free) ----
    if (c >= 0) {
        float4 bi4 = boxo[tid];
        float  ai  = area[tid];
        int k0 = cbase[c], k1 = cbase[c + 1];
        for (int k = k0; k < k1; ++k) {
            int j = clist[k];
            if (j == tid) continue;
            float4 bj = boxo[j];
            float ww = fmaxf(__fsub_rn(fminf(bi4.z, bj.z), fmaxf(bi4.x, bj.x)), 0.0f);
            float hh = fmaxf(__fsub_rn(fminf(bi4.w, bj.w), fmaxf(bi4.y, bj.y)), 0.0f);
            float inter = __fmul_rn(ww, hh);
            float den = __fadd_rn(__fsub_rn(__fadd_rn(ai, area[j]), inter), 1e-9f);
            if (__fdiv_rn(inter, den) > IOU_TH)
                rows[tid * RSTR + (j >> 5)] |= (1u << (j & 31));
        }
    }
    __syncthreads();

    // ---- Phase 7: windowed greedy scan (warp 0) ----
    if (tid < 32) {
        int nwin = (V + 31) >> 5;
        unsigned supp = 0;
        for (int widx = 0; widx < nwin; ++widx) {
            int i0 = widx << 5;
            int lim = V - i0;
            unsigned vmask = (lim >= 32) ? 0xffffffffu : ((1u << lim) - 1u);
            unsigned dw = rows[(i0 + lane) * RSTR + widx];
            unsigned ext = __shfl_sync(0xffffffffu, supp, widx);
            unsigned sw = ext | ~vmask;
            unsigned keep = 0;
            #pragma unroll
            for (int t = 0; t < 32; ++t) {
                unsigned dt = __shfl_sync(0xffffffffu, dw, t);
                if (!((sw >> t) & 1u)) { sw |= dt; keep |= (1u << t); }
            }
            unsigned acc = 0;
            #pragma unroll
            for (int t = 0; t < 32; ++t)
                if ((keep >> t) & 1u) acc |= rows[(i0 + t) * RSTR + lane];
            supp |= acc;
            if (lane == 0) keepw[widx] = keep;
        }
    }
    __syncthreads();

    // ---- Phase 8: output + self-clean ----
    if (tid < TOPK) {
        bool keep = (keepw[tid >> 5] >> (tid & 31)) & 1u;
        float4 bx = boxp[tid];
        float so  = score[tid];
        float cf  = clsf[tid];
        if (!keep) { bx = make_float4(0.f, 0.f, 0.f, 0.f); so = 0.f; cf = 0.f; }
        float* o = out + ((size_t)b * TOPK + tid) * 6;
        o[0] = bx.x; o[1] = bx.y; o[2] = bx.z; o[3] = bx.w; o[4] = so; o[5] = cf;
    }
    if (tid == 0) g_ccnt[b] = 0u;
}

// ---------------- launcher ----------------
extern "C" void kernel_launch(void* const* d_in, const int* in_sizes, int n_in,
                              void* d_out, int out_size) {
    (void)in_sizes; (void)n_in; (void)out_size;
    const float* x = (const float*)d_in[0];
    float* out = (float*)d_out;
    cudaFuncSetAttribute(k_post, cudaFuncAttributeMaxDynamicSharedMemorySize, K3_SMEM);

    k_score<<<(BATCH * NANCH) / SB, SB>>>(x);
    k_pick <<<BATCH, 1024>>>();
    k_cand <<<dim3(25, BATCH), 1024>>>();
    k_post <<<BATCH, 1024, K3_SMEM>>>(x, out);
}

// round 13
// speedup vs baseline: 1.2784x; 1.0447x over previous
#include <cuda_runtime.h>
#include <cstdint>

#define BATCH   8
#define NANCH   25200
#define NCH     85
#define TOPK    1000
#define KPAD    1024
#define NCLS    80
#define CONF_TH 0.25f
#define IOU_TH  0.45f
#define MAX_WH  4096.0f
#define NB14    16384
#define CAP     8192
#define RSTR    33

// ---------------- scratch (device globals; no allocation) ----------------
__device__ unsigned           g_enc [BATCH * NANCH];
__device__ unsigned           g_hist[BATCH * NB14];   // zeroed by k_pick after use
__device__ unsigned long long g_cand[BATCH * CAP];
__device__ unsigned           g_ccnt[BATCH];          // zeroed by k_post after use
__device__ unsigned           g_bucket[BATCH];
__device__ unsigned           g_need[BATCH];
__device__ unsigned long long g_T64[BATCH];           // 0 = needs rank step

// ---------------- K1: score = obj * max(cls); encode; fused 14-bit histogram ----------------
#define SB 128
__global__ void __launch_bounds__(SB) k_score(const float* __restrict__ x) {
    __shared__ float sx[SB * NCH];
    const int tid = threadIdx.x;
    const size_t base = (size_t)blockIdx.x * SB * NCH;
    const float4* xv = (const float4*)(x + base);
    float4* sv = (float4*)sx;
    #pragma unroll
    for (int t = tid; t < SB * NCH / 4; t += SB) sv[t] = xv[t];
    __syncthreads();

    const int a = blockIdx.x * SB + tid;
    const float* p = sx + tid * NCH;
    const float obj = p[4];

    const int off = tid * NCH + 5;
    const int pre = (-off) & 3;
    float m0 = __int_as_float(0xff800000);
    for (int k = 0; k < pre; ++k) m0 = fmaxf(m0, sx[off + k]);
    const int a0  = off + pre;
    const int n   = 80 - pre;
    const int nf4 = n >> 2;
    const int tl  = n & 3;
    const float4* pv = (const float4*)(sx + a0);
    float4 acc = pv[0];
    #pragma unroll 4
    for (int q = 1; q < nf4; ++q) {
        float4 v = pv[q];
        acc.x = fmaxf(acc.x, v.x); acc.y = fmaxf(acc.y, v.y);
        acc.z = fmaxf(acc.z, v.z); acc.w = fmaxf(acc.w, v.w);
    }
    float m = fmaxf(fmaxf(acc.x, acc.y), fmaxf(acc.z, acc.w));
    m = fmaxf(m, m0);
    const int tb = a0 + 4 * nf4;
    for (int k = 0; k < tl; ++k) m = fmaxf(m, sx[tb + k]);

    float sc = __fmul_rn(obj, m);
    unsigned u = __float_as_uint((sc > CONF_TH) ? sc : -1.0f);
    unsigned e = (u & 0x80000000u) ? ~u : (u | 0x80000000u);
    g_enc[a] = e;

    int b = a / NANCH;
    unsigned addr = (unsigned)b * NB14 + (e >> 18);
    unsigned mm = __match_any_sync(0xffffffffu, addr);
    if ((tid & 31) == (__ffs(mm) - 1))
        atomicAdd(&g_hist[addr], (unsigned)__popc(mm));
}

// ---------------- K2a: boundary bucket via register suffix scan ----------------
__global__ void __launch_bounds__(1024) k_pick() {
    const int b = blockIdx.x, tid = threadIdx.x;
    const int wid = tid >> 5, lane = tid & 31;
    __shared__ unsigned s_w[32];

    unsigned lv[16];
    const uint4* hv = (const uint4*)(g_hist + b * NB14 + tid * 16);
    #pragma unroll
    for (int q = 0; q < 4; ++q) {
        uint4 h = hv[q];
        lv[q * 4 + 0] = h.x; lv[q * 4 + 1] = h.y;
        lv[q * 4 + 2] = h.z; lv[q * 4 + 3] = h.w;
    }
    uint4* hz = (uint4*)(g_hist + b * NB14 + tid * 16);
    const uint4 z4 = make_uint4(0u, 0u, 0u, 0u);
    #pragma unroll
    for (int q = 0; q < 4; ++q) hz[q] = z4;

    unsigned run = 0;
    #pragma unroll
    for (int i = 15; i >= 0; --i) { run += lv[i]; lv[i] = run; }
    const unsigned ttot = run;
    unsigned v = ttot;
    #pragma unroll
    for (int off = 1; off < 32; off <<= 1) {
        unsigned t = __shfl_down_sync(0xffffffffu, v, off);
        if (lane + off < 32) v += t;
    }
    if (lane == 0) s_w[wid] = v;
    __syncthreads();
    if (tid < 32) {
        unsigned u0 = s_w[tid], w = u0;
        #pragma unroll
        for (int off = 1; off < 32; off <<= 1) {
            unsigned t = __shfl_down_sync(0xffffffffu, w, off);
            if (tid + off < 32) w += t;
        }
        s_w[tid] = w - u0;
    }
    __syncthreads();
    {
        const int base16 = tid * 16;
        unsigned above = s_w[wid] + (v - ttot);
        #pragma unroll
        for (int i = 0; i < 16; ++i) {
            unsigned tot = above + lv[i];
            unsigned cnt = lv[i] - ((i < 15) ? lv[i + 1] : 0u);
            unsigned gt  = tot - cnt;
            if (gt < TOPK && TOPK <= tot) {
                unsigned need = TOPK - gt;
                g_bucket[b] = (unsigned)(base16 + i);
                g_need[b]   = need;
                g_T64[b]    = (need == cnt)
                              ? ((unsigned long long)(base16 + i) << 50) : 0ull;
            }
        }
    }
}

// ---------------- K2b: compact boundary-bucket candidates (grid-wide) ----------------
__global__ void __launch_bounds__(1024) k_cand() {
    const int b = blockIdx.y;
    const int i = blockIdx.x * 1024 + threadIdx.x;
    if (i >= NANCH) return;
    unsigned e = g_enc[b * NANCH + i];
    if ((e >> 18) == g_bucket[b]) {
        unsigned pos = atomicAdd(&g_ccnt[b], 1u);
        if (pos < CAP)
            g_cand[b * CAP + pos] =
                ((unsigned long long)e << 32) | (unsigned)(~(unsigned)i);
    }
}

// ---------------- bitonic shfl stage helper (descending network) ----------------
__device__ __forceinline__ unsigned long long bsort_shfl_stage(
    unsigned long long v, int tid, unsigned kk, unsigned j) {
    unsigned long long pv = __shfl_xor_sync(0xffffffffu, v, j);
    bool upper = (tid & j) != 0;
    bool desc  = ((tid & kk) == 0);
    bool takemax = (desc != upper);   // desc & lower -> max ; asc & upper -> max
    bool pgt = pv > v;
    return (takemax == pgt) ? pv : v;
}

// ---------------- K3: rank + collect + sort + gather + sparse IoU + scan + output ----------------
#define PO_ROWS   0
#define PO_BOXO   135168
#define PO_BOXP   151552
#define PO_AREA   167936
#define PO_SCORE  172032
#define PO_CLSF   176128
#define PO_CLIST  180224
#define PO_CBASE  184320
#define PO_COFF   184832
#define PO_KEEPW  185344
#define PO_OUTK   185472
#define PO_SIDX   193664
#define PO_SCLS   197760
#define K3_SMEM   201856
// aliases inside rows region (used before rows is zeroed):
#define AL_CAND   0        // u64[CAP] = 64KB
#define AL_HIST2  65536    // u32[2048]
#define AL_SCN2   73728    // u32[2048]

__global__ void __launch_bounds__(1024) k_post(const float* __restrict__ x,
                                               float* __restrict__ out) {
    const int b   = blockIdx.x;
    const int tid = threadIdx.x;
    const int wid = tid >> 5, lane = tid & 31;
    extern __shared__ unsigned char sm[];
    unsigned* rows  = (unsigned*)(sm + PO_ROWS);
    float4*   boxo  = (float4*)  (sm + PO_BOXO);
    float4*   boxp  = (float4*)  (sm + PO_BOXP);
    float*    area  = (float*)   (sm + PO_AREA);
    float*    score = (float*)   (sm + PO_SCORE);
    float*    clsf  = (float*)   (sm + PO_CLSF);
    int*      clist = (int*)     (sm + PO_CLIST);
    int*      cbase = (int*)     (sm + PO_CBASE);
    int*      coff  = (int*)     (sm + PO_COFF);
    unsigned* keepw = (unsigned*)(sm + PO_KEEPW);
    unsigned long long* outk  = (unsigned long long*)(sm + PO_OUTK);
    int*      sidx  = (int*)     (sm + PO_SIDX);
    int*      scls  = (int*)     (sm + PO_SCLS);
    unsigned long long* cand  = (unsigned long long*)(sm + AL_CAND);
    unsigned*           hist2 = (unsigned*)(sm + AL_HIST2);
    unsigned*           scn2  = (unsigned*)(sm + AL_SCN2);
    __shared__ unsigned s_ctrl[4];
    __shared__ unsigned long long s_T64;

    const unsigned* encb = g_enc + b * NANCH;

    // ---- Phase 1: exact 1000th key T64 (rank-by-count over boundary bucket) ----
    unsigned long long T64 = g_T64[b];
    if (T64 == 0ull) {
        unsigned M0 = g_ccnt[b];
        unsigned need = g_need[b];
        unsigned C;
        if (M0 <= CAP) {
            C = M0;
            for (unsigned j = tid; j < C; j += 1024) cand[j] = g_cand[b * CAP + j];
            __syncthreads();
        } else {
            unsigned long long prefix = (unsigned long long)g_bucket[b];
            int shift = 50;
            unsigned count = M0;
            while (count > CAP) {
                int w = (shift >= 11) ? 11 : shift;
                int s2 = shift - w;
                unsigned dmask = (1u << w) - 1u;
                for (int t = tid; t < 2048; t += 1024) hist2[t] = 0u;
                __syncthreads();
                for (int it = 0; it < 25; ++it) {
                    int i = tid + it * 1024;
                    if (i < NANCH) {
                        unsigned long long key =
                            ((unsigned long long)encb[i] << 32) | (unsigned)(~(unsigned)i);
                        if ((key >> shift) == prefix)
                            atomicAdd(&hist2[(unsigned)((key >> s2) & dmask)], 1u);
                    }
                }
                __syncthreads();
                for (int t = tid; t < 2048; t += 1024) scn2[t] = hist2[t];
                __syncthreads();
                for (int d = 1; d < 2048; d <<= 1) {
                    unsigned a0 = (tid + d < 2048) ? scn2[tid + d] : 0u;
                    unsigned a1 = (tid + 1024 + d < 2048) ? scn2[tid + 1024 + d] : 0u;
                    __syncthreads();
                    scn2[tid] += a0; scn2[tid + 1024] += a1;
                    __syncthreads();
                }
                #pragma unroll
                for (int q = 0; q < 2; ++q) {
                    int d = tid + q * 1024;
                    unsigned tot = scn2[d], gt = tot - hist2[d];
                    if (gt < need && need <= tot) {
                        s_ctrl[0] = (unsigned)d;
                        s_ctrl[1] = need - gt;
                        s_ctrl[2] = hist2[d];
                    }
                }
                __syncthreads();
                prefix = (prefix << w) | (unsigned long long)s_ctrl[0];
                need = s_ctrl[1]; count = s_ctrl[2]; shift = s2;
                __syncthreads();
            }
            if (tid == 0) s_ctrl[3] = 0u;
            __syncthreads();
            for (int it = 0; it < 25; ++it) {
                int i = tid + it * 1024;
                if (i < NANCH) {
                    unsigned long long key =
                        ((unsigned long long)encb[i] << 32) | (unsigned)(~(unsigned)i);
                    if ((key >> shift) == prefix) {
                        unsigned pos = atomicAdd(&s_ctrl[3], 1u);
                        if (pos < CAP) cand[pos] = key;
                    }
                }
            }
            __syncthreads();
            C = s_ctrl[3];
        }
        for (unsigned j = tid; j < C; j += 1024) {
            unsigned long long kj = cand[j];
            unsigned gt = 0;
            for (unsigned k = 0; k < C; ++k) gt += (cand[k] > kj);
            if (gt == need - 1) s_T64 = kj;
        }
        __syncthreads();
        T64 = s_T64;
    }

    // ---- Phase 2: collect the exactly-1000 keys >= T64 ----
    if (tid == 0) s_ctrl[3] = 0u;
    __syncthreads();
    #pragma unroll 5
    for (int it = 0; it < 25; ++it) {
        int i = tid + it * 1024;
        if (i < NANCH) {
            unsigned long long key =
                ((unsigned long long)encb[i] << 32) | (unsigned)(~(unsigned)i);
            if (key >= T64) {
                unsigned pos = atomicAdd(&s_ctrl[3], 1u);
                if (pos < KPAD) outk[pos] = key;
            }
        }
    }
    __syncthreads();
    const unsigned ncol = (s_ctrl[3] < KPAD) ? s_ctrl[3] : KPAD;
    if (tid >= (int)ncol) outk[tid] = 0ull;
    __syncthreads();

    // ---- Phase 3: hybrid bitonic sort 1024 desc (shfl for j<32, smem for j>=32) ----
    {
        unsigned long long v = outk[tid];
        // kk = 2..32: fully in registers
        #pragma unroll
        for (unsigned kk = 2; kk <= 32; kk <<= 1)
            for (unsigned j = kk >> 1; j > 0; j >>= 1)
                v = bsort_shfl_stage(v, tid, kk, j);
        outk[tid] = v;
        __syncthreads();
        // kk = 64..1024: smem stages for j>=32, then register stages for j<32
        for (unsigned kk = 64; kk <= 1024; kk <<= 1) {
            for (unsigned j = kk >> 1; j >= 32; j >>= 1) {
                unsigned i = (unsigned)tid, ixj = i ^ j;
                if (ixj > i) {
                    unsigned long long a = outk[i], bb = outk[ixj];
                    bool desc = ((i & kk) == 0);
                    if (desc ? (a < bb) : (a > bb)) { outk[i] = bb; outk[ixj] = a; }
                }
                __syncthreads();
            }
            v = outk[tid];
            #pragma unroll
            for (unsigned j = 16; j > 0; j >>= 1)
                v = bsort_shfl_stage(v, tid, kk, j);
            outk[tid] = v;
            __syncthreads();
        }
    }

    // ---- Phase 4: zero bitmat; decode; pipelined warp-per-row gather + argmax ----
    for (int t = tid; t < KPAD * RSTR; t += 1024) rows[t] = 0u;
    if (tid < NCLS) coff[tid] = 0;
    if (tid < 32)   keepw[tid] = 0u;

    unsigned long long key = outk[tid];
    float sc = -1.0f;
    int   idx = -1;
    if (key != 0ull) {
        unsigned e = (unsigned)(key >> 32);
        unsigned u = (e & 0x80000000u) ? (e ^ 0x80000000u) : ~e;
        sc = __uint_as_float(u);
        idx = (int)(~(unsigned)(key & 0xffffffffull));
    }
    score[tid] = sc;
    sidx[tid]  = (tid < TOPK) ? idx : -1;
    scls[tid]  = -1;
    boxp[tid] = make_float4(0.f, 0.f, 0.f, 0.f);
    boxo[tid] = make_float4(0.f, 0.f, 0.f, 0.f);
    area[tid] = 0.f; clsf[tid] = 0.f;
    __syncthreads();

    // warp-per-row, software-pipelined: prefetch row r+32 while reducing row r
    {
        int r = wid;
        float v0 = 0.f, v1 = 0.f, v2 = 0.f;
        if (r < TOPK) {
            const float* p = x + ((size_t)b * NANCH + sidx[r]) * NCH;
            v0 = p[lane]; v1 = p[32 + lane];
            v2 = (lane < 21) ? p[64 + lane] : 0.0f;
        }
        while (r < TOPK) {
            int rn = r + 32;
            float n0 = 0.f, n1 = 0.f, n2 = 0.f;
            if (rn < TOPK) {
                const float* pn = x + ((size_t)b * NANCH + sidx[rn]) * NCH;
                n0 = pn[lane]; n1 = pn[32 + lane];
                n2 = (lane < 21) ? pn[64 + lane] : 0.0f;
            }
            // reduce current row
            float best = __int_as_float(0xff800000);
            int   bi   = 1 << 30;
            if (lane >= 5)              { best = v0; bi = lane - 5;  }
            if (v1 > best)              { best = v1; bi = 27 + lane; }
            if (lane < 21 && v2 > best) { best = v2; bi = 59 + lane; }
            #pragma unroll
            for (int o = 16; o; o >>= 1) {
                float ov = __shfl_down_sync(0xffffffffu, best, o);
                int   oi = __shfl_down_sync(0xffffffffu, bi, o);
                if (ov > best || (ov == best && oi < bi)) { best = ov; bi = oi; }
            }
            float cx = __shfl_sync(0xffffffffu, v0, 0);
            float cy = __shfl_sync(0xffffffffu, v0, 1);
            float w  = __shfl_sync(0xffffffffu, v0, 2);
            float h  = __shfl_sync(0xffffffffu, v0, 3);
            if (lane == 0) {
                float hw = __fmul_rn(w, 0.5f), hh = __fmul_rn(h, 0.5f);
                float x1 = __fsub_rn(cx, hw), y1 = __fsub_rn(cy, hh);
                float x2 = __fadd_rn(cx, hw), y2 = __fadd_rn(cy, hh);
                float cf = (float)bi;
                float o2 = __fmul_rn(cf, MAX_WH);
                float ox1 = __fadd_rn(x1, o2), oy1 = __fadd_rn(y1, o2);
                float ox2 = __fadd_rn(x2, o2), oy2 = __fadd_rn(y2, o2);
                boxp[r] = make_float4(x1, y1, x2, y2);
                boxo[r] = make_float4(ox1, oy1, ox2, oy2);
                area[r] = __fmul_rn(__fsub_rn(ox2, ox1), __fsub_rn(oy2, oy1));
                clsf[r] = cf;
                scls[r] = bi;
            }
            r = rn; v0 = n0; v1 = n1; v2 = n2;
        }
    }
    __syncthreads();
    const int c = scls[tid];
    int V = __syncthreads_count(tid < TOPK && score[tid] > CONF_TH);

    // ---- Phase 5: counting sort by class (cross-class IoU exactly 0) ----
    if (c >= 0) atomicAdd(&coff[c], 1);
    __syncthreads();
    if (tid == 0) {
        int r2 = 0;
        #pragma unroll
        for (int k = 0; k < NCLS; ++k) { cbase[k] = r2; r2 += coff[k]; }
        cbase[NCLS] = r2;
    }
    __syncthreads();
    if (tid < NCLS) coff[tid] = cbase[tid];
    __syncthreads();
    if (c >= 0) clist[atomicAdd(&coff[c], 1)] = tid;
    __syncthreads();

    // ---- Phase 6: sparse IoU (reference fp32 arithmetic, FMA-free) ----
    if (c >= 0) {
        float4 bi4 = boxo[tid];
        float  ai  = area[tid];
        int k0 = cbase[c], k1 = cbase[c + 1];
        for (int k = k0; k < k1; ++k) {
            int j = clist[k];
            if (j == tid) continue;
            float4 bj = boxo[j];
            float ww = fmaxf(__fsub_rn(fminf(bi4.z, bj.z), fmaxf(bi4.x, bj.x)), 0.0f);
            float hh = fmaxf(__fsub_rn(fminf(bi4.w, bj.w), fmaxf(bi4.y, bj.y)), 0.0f);
            float inter = __fmul_rn(ww, hh);
            float den = __fadd_rn(__fsub_rn(__fadd_rn(ai, area[j]), inter), 1e-9f);
            if (__fdiv_rn(inter, den) > IOU_TH)
                rows[tid * RSTR + (j >> 5)] |= (1u << (j & 31));
        }
    }
    __syncthreads();

    // ---- Phase 7: windowed greedy scan (warp 0) ----
    if (tid < 32) {
        int nwin = (V + 31) >> 5;
        unsigned supp = 0;
        for (int widx = 0; widx < nwin; ++widx) {
            int i0 = widx << 5;
            int lim = V - i0;
            unsigned vmask = (lim >= 32) ? 0xffffffffu : ((1u << lim) - 1u);
            unsigned dw = rows[(i0 + lane) * RSTR + widx];
            unsigned ext = __shfl_sync(0xffffffffu, supp, widx);
            unsigned sw = ext | ~vmask;
            unsigned keep = 0;
            #pragma unroll
            for (int t = 0; t < 32; ++t) {
                unsigned dt = __shfl_sync(0xffffffffu, dw, t);
                if (!((sw >> t) & 1u)) { sw |= dt; keep |= (1u << t); }
            }
            unsigned acc = 0;
            #pragma unroll
            for (int t = 0; t < 32; ++t)
                if ((keep >> t) & 1u) acc |= rows[(i0 + t) * RSTR + lane];
            supp |= acc;
            if (lane == 0) keepw[widx] = keep;
        }
    }
    __syncthreads();

    // ---- Phase 8: output + self-clean ----
    if (tid < TOPK) {
        bool keep = (keepw[tid >> 5] >> (tid & 31)) & 1u;
        float4 bx = boxp[tid];
        float so  = score[tid];
        float cf  = clsf[tid];
        if (!keep) { bx = make_float4(0.f, 0.f, 0.f, 0.f); so = 0.f; cf = 0.f; }
        float* o = out + ((size_t)b * TOPK + tid) * 6;
        o[0] = bx.x; o[1] = bx.y; o[2] = bx.z; o[3] = bx.w; o[4] = so; o[5] = cf;
    }
    if (tid == 0) g_ccnt[b] = 0u;
}

// ---------------- launcher ----------------
extern "C" void kernel_launch(void* const* d_in, const int* in_sizes, int n_in,
                              void* d_out, int out_size) {
    (void)in_sizes; (void)n_in; (void)out_size;
    const float* x = (const float*)d_in[0];
    float* out = (float*)d_out;
    cudaFuncSetAttribute(k_post, cudaFuncAttributeMaxDynamicSharedMemorySize, K3_SMEM);

    k_score<<<(BATCH * NANCH) / SB, SB>>>(x);
    k_pick <<<BATCH, 1024>>>();
    k_cand <<<dim3(25, BATCH), 1024>>>();
    k_post <<<BATCH, 1024, K3_SMEM>>>(x, out);
}